// round 16
// baseline (speedup 1.0000x reference)
#include <cuda_runtime.h>
#include <cuda_fp16.h>
#include <cstdint>
#include <math.h>

// ============================================================================
// Fused Node2Prop2, mma.sync single-term fp16 (base sm_103 target).
//   H = fp16(X) @ fp16(W1), fp32 accum (rel_err 5.66e-4, measured r7-r13).
//   out[g] += sum_nodes ( softplus(H + b1) - ln2 ) @ W2
// Round 14: r12 config (6 streams/SMSP: 3 groups x 128 thr, 2 CTAs/SM) with a
// restructured tile loop: ONE barrier per tile, next-tile LDG issued right
// after the MMAs and hidden under the MUFU epilogue (2 waves), s_partial
// double-buffered so scatter overlaps the next tile's compute.
// ============================================================================

#define NTHREADS 384
#define NGROUPS  3
#define TILE_M   32

#define XH_ROWB  272         // fp16 x row bytes (136 halves; 16B-aligned, shifted)
#define XHB      (32 * XH_ROWB)               // 8704 per buffer
#define WSTRIDE  136
#define WBYTES   (128 * WSTRIDE * 2)          // 34816
#define OFF_X    WBYTES
#define SMEM_DYN (WBYTES + NGROUPS * 2 * XHB)  // 87040 -> 2 CTAs/SM

#define LOG2E 1.4426950408889634f
#define LN2   0.6931471805599453f

// ---------------- helpers ---------------------------------------------------

__device__ __forceinline__ uint32_t smem_u32(const void* p) {
    uint32_t a;
    asm("{ .reg .u64 t; cvta.to.shared.u64 t, %1; cvt.u32.u64 %0, t; }"
        : "=r"(a) : "l"(p));
    return a;
}

__device__ __forceinline__ void group_bar(int g) {
    asm volatile("bar.sync %0, 128;" :: "r"(g + 1) : "memory");
}

__device__ __forceinline__ void ldmatrix_x4(uint32_t& r0, uint32_t& r1,
                                            uint32_t& r2, uint32_t& r3,
                                            uint32_t addr) {
    asm volatile("ldmatrix.sync.aligned.m8n8.x4.shared.b16 {%0,%1,%2,%3}, [%4];"
                 : "=r"(r0), "=r"(r1), "=r"(r2), "=r"(r3) : "r"(addr));
}

__device__ __forceinline__ void mma_f32acc(float* d, const uint32_t* a,
                                           uint32_t b0, uint32_t b1) {
    asm volatile(
        "mma.sync.aligned.m16n8k16.row.col.f32.f16.f16.f32 "
        "{%0,%1,%2,%3}, {%4,%5,%6,%7}, {%8,%9}, {%0,%1,%2,%3};"
        : "+f"(d[0]), "+f"(d[1]), "+f"(d[2]), "+f"(d[3])
        : "r"(a[0]), "r"(a[1]), "r"(a[2]), "r"(a[3]), "r"(b0), "r"(b1));
}

__device__ __forceinline__ uint32_t pack_f16(float lo, float hi) {
    uint32_t r;
    asm("cvt.rn.f16x2.f32 %0, %1, %2;" : "=r"(r) : "f"(hi), "f"(lo));
    return r;
}

__device__ __forceinline__ void sts128(uint32_t a, uint32_t r0, uint32_t r1,
                                       uint32_t r2, uint32_t r3) {
    asm volatile("st.shared.v4.b32 [%0], {%1,%2,%3,%4};"
                 :: "r"(a), "r"(r0), "r"(r1), "r"(r2), "r"(r3) : "memory");
}

__device__ __forceinline__ float2 ldsf2(uint32_t a) {
    float2 v;
    asm volatile("ld.shared.v2.f32 {%0, %1}, [%2];"
                 : "=f"(v.x), "=f"(v.y) : "r"(a));
    return v;
}

// p += (softplus(acc + b1) - ln2) * w2, with the -ln2*w2 constant hoisted.
__device__ __forceinline__ void sp_acc(float& p, float acc, float bl2, float w2l2) {
    float w = fmaf(acc, LOG2E, bl2);
    float e, l;
    asm("ex2.approx.f32 %0, %1;" : "=f"(e) : "f"(w));
    asm("lg2.approx.f32 %0, %1;" : "=f"(l) : "f"(1.0f + e));
    p = fmaf(l, w2l2, p);
}

// ---------------- prepped W1: fp16, transposed [j][k], padded stride --------

__device__ unsigned short g_wh[128 * WSTRIDE];

__global__ void prep_w1(const float* __restrict__ W1, float* __restrict__ out,
                        int out_n) {
    int idx = blockIdx.x * blockDim.x + threadIdx.x;
    if (idx < 128 * 128) {
        int j = idx >> 7;
        int k = idx & 127;
        g_wh[j * WSTRIDE + k] = __half_as_ushort(__float2half_rn(W1[k * 128 + j]));
    }
    if (idx < out_n) out[idx] = 0.0f;
}

// ---------------- main persistent kernel ------------------------------------

__global__ void __launch_bounds__(NTHREADS, 2)
fused_mlp_hmma(const float* __restrict__ x,
               const float* __restrict__ b1,
               const float* __restrict__ W2,
               const int*   __restrict__ batch,
               float* __restrict__ out,
               int n_nodes, int n_tiles)
{
    extern __shared__ char dsm[];
    const uint32_t sbase = smem_u32(dsm);
    const uint32_t whb = sbase;                  // W tile at offset 0

    __shared__ float s_b1l2[128];
    __shared__ float s_w2l2[128];
    __shared__ float s_partial[NGROUPS][2][4][32];   // double-buffered

    const int tid  = threadIdx.x;
    const int wid  = tid >> 5;
    const int lane = tid & 31;
    const int g    = wid >> 2;         // group 0..2 (one warp per SMSP each)
    const int wg   = wid & 3;          // warp's 32-col block
    const int t128 = tid & 127;
    const int qc   = lane & 3;
    const int qr   = lane >> 2;

    const uint32_t xgrp = sbase + OFF_X + (uint32_t)g * (2 * XHB);

    // ---- prologue: stage W, consts ----------------------------------------
    {
        const uint4* gh = (const uint4*)g_wh;
        uint4* sh = (uint4*)dsm;
        for (int i = tid; i < WBYTES / 16; i += NTHREADS)
            sh[i] = gh[i];
    }
    if (tid < 128) {
        s_b1l2[tid] = b1[tid] * LOG2E;
        s_w2l2[tid] = W2[tid] * LN2;
    }
    __syncthreads();

    // per-thread constant: sum of w2*ln2 over this thread's 8 columns
    float c0 = 0.0f;
    const uint32_t jb0 = (uint32_t)((wg * 32 + 2 * qc) * 4);
    const uint32_t bbs = smem_u32(s_b1l2) + jb0;
    const uint32_t wbs = smem_u32(s_w2l2) + jb0;
    {
        #pragma unroll
        for (int j8 = 0; j8 < 4; j8++) {
            float2 w = ldsf2(wbs + (uint32_t)(j8 * 32));
            c0 += w.x + w.y;
        }
    }

    // B ldmatrix lane base addresses (2 blocks of 16 j-rows each)
    uint32_t bbase[2];
    {
        const uint32_t l8 = lane & 7;
        const uint32_t gsel = lane >> 3;
        #pragma unroll
        for (int ntp = 0; ntp < 2; ntp++) {
            uint32_t jrow = (uint32_t)(wg * 32 + ntp * 16) + ((gsel & 1) << 3) + l8;
            bbase[ntp] = whb + jrow * (WSTRIDE * 2) + (((gsel >> 1) << 3) << 1);
        }
    }
    // A ldmatrix lane base offsets within an x buffer (per mt: 16-row halves)
    uint32_t abase[2];
    {
        const uint32_t l8 = lane & 7;
        const uint32_t rsel = (lane >> 3) & 1;
        const uint32_t ksel = (lane >> 4) & 1;
        #pragma unroll
        for (int mt = 0; mt < 2; mt++) {
            uint32_t row = (uint32_t)(mt * 16) + rsel * 8 + l8;
            abase[mt] = row * XH_ROWB + ksel * 16;
        }
    }

    const int GS = gridDim.x * NGROUPS;
    const int t0 = blockIdx.x * NGROUPS + g;
    const int T = (t0 < n_tiles) ? ((n_tiles - 1 - t0) / GS + 1) : 0;

    // staging geometry: 128 threads, chunk c = rows c*8..c*8+7
    const int lrow_off = t128 >> 4;
    const int lcol     = (t128 & 15) * 8;
    const uint32_t sts_off = (uint32_t)(lrow_off * XH_ROWB) + (uint32_t)(lcol * 2);

    // epilogue over a j8 range (softplus + dot W2)
    #define EPI_RANGE(p, acc, LO, HI)                                          \
        _Pragma("unroll")                                                      \
        for (int j8 = (LO); j8 < (HI); j8++) {                                 \
            float2 bb = ldsf2(bbs + (uint32_t)(j8 * 32));                      \
            float2 ww = ldsf2(wbs + (uint32_t)(j8 * 32));                      \
            _Pragma("unroll")                                                  \
            for (int mt = 0; mt < 2; mt++) {                                   \
                sp_acc(p[mt][0], acc[mt][j8][0], bb.x, ww.x);                  \
                sp_acc(p[mt][0], acc[mt][j8][1], bb.y, ww.y);                  \
                sp_acc(p[mt][1], acc[mt][j8][2], bb.x, ww.x);                  \
                sp_acc(p[mt][1], acc[mt][j8][3], bb.y, ww.y);                  \
            }                                                                  \
        }

    if (T > 0) {
        // prologue stage of tile 0 into buffer 0
        {
            const float* src = x + (size_t)t0 * TILE_M * 128 + lcol;
            uint32_t dst = xgrp + sts_off;
            #pragma unroll
            for (int c = 0; c < 4; c++) {
                int row = c * 8 + lrow_off;
                float4 v0 = make_float4(0.f, 0.f, 0.f, 0.f), v1 = v0;
                if ((size_t)t0 * TILE_M + row < (size_t)n_nodes) {
                    v0 = *(const float4*)(src + (size_t)row * 128);
                    v1 = *(const float4*)(src + (size_t)row * 128 + 4);
                }
                sts128(dst + (uint32_t)(c * 8 * XH_ROWB),
                       pack_f16(v0.x, v0.y), pack_f16(v0.z, v0.w),
                       pack_f16(v1.x, v1.y), pack_f16(v1.z, v1.w));
            }
        }
        group_bar(g);

        for (int i = 0; i < T; i++) {
            const uint32_t xb = xgrp + (uint32_t)(i & 1) * XHB;

            // ---- MMA loop: acc[mt][j8][4] ----------------------------------
            float acc[2][4][4];
            #pragma unroll
            for (int mt = 0; mt < 2; mt++)
                #pragma unroll
                for (int j8 = 0; j8 < 4; j8++)
                    #pragma unroll
                    for (int e = 0; e < 4; e++) acc[mt][j8][e] = 0.0f;

            #pragma unroll
            for (int ks = 0; ks < 8; ks++) {
                uint32_t A0[4], A1[4];
                ldmatrix_x4(A0[0], A0[1], A0[2], A0[3],
                            xb + abase[0] + (uint32_t)(ks * 32));
                ldmatrix_x4(A1[0], A1[1], A1[2], A1[3],
                            xb + abase[1] + (uint32_t)(ks * 32));
                #pragma unroll
                for (int ntp = 0; ntp < 2; ntp++) {
                    uint32_t h0, h1, h2, h3;
                    ldmatrix_x4(h0, h1, h2, h3, bbase[ntp] + (uint32_t)(ks * 32));
                    mma_f32acc(acc[0][ntp * 2],     A0, h0, h2);
                    mma_f32acc(acc[0][ntp * 2 + 1], A0, h1, h3);
                    mma_f32acc(acc[1][ntp * 2],     A1, h0, h2);
                    mma_f32acc(acc[1][ntp * 2 + 1], A1, h1, h3);
                }
            }

            // ---- next-tile prefetch setup ----------------------------------
            const bool hn = (i + 1 < T);
            const long tnext = (long)t0 + (long)(i + 1) * GS;
            const float* srcn = x + (size_t)(hn ? tnext : 0) * TILE_M * 128 + lcol;
            const uint32_t xn = xgrp + (uint32_t)((i + 1) & 1) * XHB + sts_off;

            // prefetch scatter index (independent LDG, hidden under epilogue)
            int gidx = -1;
            if (t128 < 32) {
                long gn = ((long)t0 + (long)i * GS) * TILE_M + t128;
                if (gn < n_nodes) gidx = batch[gn];
            }

            float4 v0[2], v1[2];
            // LDG wave 1: chunks 0,1 (latency hidden under epi half 1)
            if (hn) {
                #pragma unroll
                for (int c = 0; c < 2; c++) {
                    int row = c * 8 + lrow_off;
                    v0[c] = make_float4(0.f, 0.f, 0.f, 0.f); v1[c] = v0[c];
                    if (tnext * TILE_M + row < (long)n_nodes) {
                        v0[c] = *(const float4*)(srcn + (size_t)row * 128);
                        v1[c] = *(const float4*)(srcn + (size_t)row * 128 + 4);
                    }
                }
            }

            float p[2][2];
            p[0][0] = p[0][1] = p[1][0] = p[1][1] = -c0;
            EPI_RANGE(p, acc, 0, 2)       // MUFU half 1 hides LDG wave 1

            if (hn) {
                #pragma unroll
                for (int c = 0; c < 2; c++)
                    sts128(xn + (uint32_t)(c * 8 * XH_ROWB),
                           pack_f16(v0[c].x, v0[c].y), pack_f16(v0[c].z, v0[c].w),
                           pack_f16(v1[c].x, v1[c].y), pack_f16(v1[c].z, v1[c].w));
                // LDG wave 2: chunks 2,3
                #pragma unroll
                for (int c = 0; c < 2; c++) {
                    int row = (c + 2) * 8 + lrow_off;
                    v0[c] = make_float4(0.f, 0.f, 0.f, 0.f); v1[c] = v0[c];
                    if (tnext * TILE_M + row < (long)n_nodes) {
                        v0[c] = *(const float4*)(srcn + (size_t)row * 128);
                        v1[c] = *(const float4*)(srcn + (size_t)row * 128 + 4);
                    }
                }
            }

            EPI_RANGE(p, acc, 2, 4)       // MUFU half 2 hides LDG wave 2

            // quad reduce + stage partials (also hides wave-2 latency)
            #pragma unroll
            for (int mt = 0; mt < 2; mt++)
                #pragma unroll
                for (int rr = 0; rr < 2; rr++) {
                    p[mt][rr] += __shfl_xor_sync(0xffffffffu, p[mt][rr], 1);
                    p[mt][rr] += __shfl_xor_sync(0xffffffffu, p[mt][rr], 2);
                }
            if (qc == 0) {
                #pragma unroll
                for (int mt = 0; mt < 2; mt++) {
                    s_partial[g][i & 1][wg][mt * 16 + qr]     = p[mt][0];
                    s_partial[g][i & 1][wg][mt * 16 + qr + 8] = p[mt][1];
                }
            }

            if (hn) {
                #pragma unroll
                for (int c = 0; c < 2; c++)
                    sts128(xn + (uint32_t)((c + 2) * 8 * XH_ROWB),
                           pack_f16(v0[c].x, v0[c].y), pack_f16(v0[c].z, v0[c].w),
                           pack_f16(v1[c].x, v1[c].y), pack_f16(v1[c].z, v1[c].w));
            }

            group_bar(g);   // single barrier: partials + next-buffer STS

            // scatter overlaps the next iteration (s_partial double-buffered)
            if (gidx >= 0) {
                float v = s_partial[g][i & 1][0][t128] + s_partial[g][i & 1][1][t128]
                        + s_partial[g][i & 1][2][t128] + s_partial[g][i & 1][3][t128];
                atomicAdd(&out[gidx], v);
            }
        }
    }
    #undef EPI_RANGE
}

// ---------------- launch -----------------------------------------------------

extern "C" void kernel_launch(void* const* d_in, const int* in_sizes, int n_in,
                              void* d_out, int out_size)
{
    const float* x     = (const float*)d_in[0];
    const float* W1    = (const float*)d_in[1];
    const float* b1    = (const float*)d_in[2];
    const float* W2    = (const float*)d_in[3];
    const int*   batch = (const int*)d_in[4];
    float* out = (float*)d_out;

    const int n_nodes = in_sizes[0] / 128;
    const int n_tiles = (n_nodes + TILE_M - 1) / TILE_M;

    prep_w1<<<64, 256>>>(W1, out, out_size);

    cudaFuncSetAttribute(fused_mlp_hmma,
                         cudaFuncAttributeMaxDynamicSharedMemorySize, SMEM_DYN);

    int sms = 148;
    cudaDeviceGetAttribute(&sms, cudaDevAttrMultiProcessorCount, 0);
    int work = (n_tiles + NGROUPS - 1) / NGROUPS;
    int grid = (work < 2 * sms) ? work : 2 * sms;

    fused_mlp_hmma<<<grid, NTHREADS, SMEM_DYN>>>(x, b1, W2, batch, out,
                                                 n_nodes, n_tiles);
}

// round 17
// speedup vs baseline: 1.0144x; 1.0144x over previous
#include <cuda_runtime.h>
#include <cuda_fp16.h>
#include <cstdint>
#include <math.h>

// ============================================================================
// Fused Node2Prop2, mma.sync single-term fp16 (base sm_103 target).
//   H = fp16(X) @ fp16(W1), fp32 accum (rel_err 5.66e-4, measured r7-r13).
//   out[g] += sum_nodes ( softplus(H + b1) - ln2 ) @ W2
// Round 14: r12 config (6 streams/SMSP: 3 groups x 128 thr, 2 CTAs/SM) with a
// restructured tile loop: ONE barrier per tile, next-tile LDG issued right
// after the MMAs and hidden under the MUFU epilogue (2 waves), s_partial
// double-buffered so scatter overlaps the next tile's compute.
// ============================================================================

#define NTHREADS 384
#define NGROUPS  3
#define TILE_M   32

#define XH_ROWB  272         // fp16 x row bytes (136 halves; 16B-aligned, shifted)
#define XHB      (32 * XH_ROWB)               // 8704 per buffer
#define WSTRIDE  136
#define WBYTES   (128 * WSTRIDE * 2)          // 34816
#define OFF_X    WBYTES
#define SMEM_DYN (WBYTES + NGROUPS * 2 * XHB)  // 87040 -> 2 CTAs/SM

#define LOG2E 1.4426950408889634f
#define LN2   0.6931471805599453f

// ---------------- helpers ---------------------------------------------------

__device__ __forceinline__ uint32_t smem_u32(const void* p) {
    uint32_t a;
    asm("{ .reg .u64 t; cvta.to.shared.u64 t, %1; cvt.u32.u64 %0, t; }"
        : "=r"(a) : "l"(p));
    return a;
}

__device__ __forceinline__ void group_bar(int g) {
    asm volatile("bar.sync %0, 128;" :: "r"(g + 1) : "memory");
}

__device__ __forceinline__ void ldmatrix_x4(uint32_t& r0, uint32_t& r1,
                                            uint32_t& r2, uint32_t& r3,
                                            uint32_t addr) {
    asm volatile("ldmatrix.sync.aligned.m8n8.x4.shared.b16 {%0,%1,%2,%3}, [%4];"
                 : "=r"(r0), "=r"(r1), "=r"(r2), "=r"(r3) : "r"(addr));
}

__device__ __forceinline__ void mma_f32acc(float* d, const uint32_t* a,
                                           uint32_t b0, uint32_t b1) {
    asm volatile(
        "mma.sync.aligned.m16n8k16.row.col.f32.f16.f16.f32 "
        "{%0,%1,%2,%3}, {%4,%5,%6,%7}, {%8,%9}, {%0,%1,%2,%3};"
        : "+f"(d[0]), "+f"(d[1]), "+f"(d[2]), "+f"(d[3])
        : "r"(a[0]), "r"(a[1]), "r"(a[2]), "r"(a[3]), "r"(b0), "r"(b1));
}

__device__ __forceinline__ uint32_t pack_f16(float lo, float hi) {
    uint32_t r;
    asm("cvt.rn.f16x2.f32 %0, %1, %2;" : "=r"(r) : "f"(hi), "f"(lo));
    return r;
}

__device__ __forceinline__ void sts128(uint32_t a, uint32_t r0, uint32_t r1,
                                       uint32_t r2, uint32_t r3) {
    asm volatile("st.shared.v4.b32 [%0], {%1,%2,%3,%4};"
                 :: "r"(a), "r"(r0), "r"(r1), "r"(r2), "r"(r3) : "memory");
}

__device__ __forceinline__ float2 ldsf2(uint32_t a) {
    float2 v;
    asm volatile("ld.shared.v2.f32 {%0, %1}, [%2];"
                 : "=f"(v.x), "=f"(v.y) : "r"(a));
    return v;
}

// p += (softplus(acc + b1) - ln2) * w2, with the -ln2*w2 constant hoisted.
__device__ __forceinline__ void sp_acc(float& p, float acc, float bl2, float w2l2) {
    float w = fmaf(acc, LOG2E, bl2);
    float e, l;
    asm("ex2.approx.f32 %0, %1;" : "=f"(e) : "f"(w));
    asm("lg2.approx.f32 %0, %1;" : "=f"(l) : "f"(1.0f + e));
    p = fmaf(l, w2l2, p);
}

// ---------------- prepped W1: fp16, transposed [j][k], padded stride --------

__device__ unsigned short g_wh[128 * WSTRIDE];

__global__ void prep_w1(const float* __restrict__ W1, float* __restrict__ out,
                        int out_n) {
    int idx = blockIdx.x * blockDim.x + threadIdx.x;
    if (idx < 128 * 128) {
        int j = idx >> 7;
        int k = idx & 127;
        g_wh[j * WSTRIDE + k] = __half_as_ushort(__float2half_rn(W1[k * 128 + j]));
    }
    if (idx < out_n) out[idx] = 0.0f;
}

// ---------------- main persistent kernel ------------------------------------

__global__ void __launch_bounds__(NTHREADS, 2)
fused_mlp_hmma(const float* __restrict__ x,
               const float* __restrict__ b1,
               const float* __restrict__ W2,
               const int*   __restrict__ batch,
               float* __restrict__ out,
               int n_nodes, int n_tiles)
{
    extern __shared__ char dsm[];
    const uint32_t sbase = smem_u32(dsm);
    const uint32_t whb = sbase;                  // W tile at offset 0

    __shared__ float s_b1l2[128];
    __shared__ float s_w2l2[128];
    __shared__ float s_partial[NGROUPS][2][4][32];   // double-buffered

    const int tid  = threadIdx.x;
    const int wid  = tid >> 5;
    const int lane = tid & 31;
    const int g    = wid >> 2;         // group 0..2 (one warp per SMSP each)
    const int wg   = wid & 3;          // warp's 32-col block
    const int t128 = tid & 127;
    const int qc   = lane & 3;
    const int qr   = lane >> 2;

    const uint32_t xgrp = sbase + OFF_X + (uint32_t)g * (2 * XHB);

    // ---- prologue: stage W, consts ----------------------------------------
    {
        const uint4* gh = (const uint4*)g_wh;
        uint4* sh = (uint4*)dsm;
        for (int i = tid; i < WBYTES / 16; i += NTHREADS)
            sh[i] = gh[i];
    }
    if (tid < 128) {
        s_b1l2[tid] = b1[tid] * LOG2E;
        s_w2l2[tid] = W2[tid] * LN2;
    }
    __syncthreads();

    // per-thread constant: sum of w2*ln2 over this thread's 8 columns
    float c0 = 0.0f;
    const uint32_t jb0 = (uint32_t)((wg * 32 + 2 * qc) * 4);
    const uint32_t bbs = smem_u32(s_b1l2) + jb0;
    const uint32_t wbs = smem_u32(s_w2l2) + jb0;
    {
        #pragma unroll
        for (int j8 = 0; j8 < 4; j8++) {
            float2 w = ldsf2(wbs + (uint32_t)(j8 * 32));
            c0 += w.x + w.y;
        }
    }

    // B ldmatrix lane base addresses (2 blocks of 16 j-rows each)
    uint32_t bbase[2];
    {
        const uint32_t l8 = lane & 7;
        const uint32_t gsel = lane >> 3;
        #pragma unroll
        for (int ntp = 0; ntp < 2; ntp++) {
            uint32_t jrow = (uint32_t)(wg * 32 + ntp * 16) + ((gsel & 1) << 3) + l8;
            bbase[ntp] = whb + jrow * (WSTRIDE * 2) + (((gsel >> 1) << 3) << 1);
        }
    }
    // A ldmatrix lane base offsets within an x buffer (per mt: 16-row halves)
    uint32_t abase[2];
    {
        const uint32_t l8 = lane & 7;
        const uint32_t rsel = (lane >> 3) & 1;
        const uint32_t ksel = (lane >> 4) & 1;
        #pragma unroll
        for (int mt = 0; mt < 2; mt++) {
            uint32_t row = (uint32_t)(mt * 16) + rsel * 8 + l8;
            abase[mt] = row * XH_ROWB + ksel * 16;
        }
    }

    const int GS = gridDim.x * NGROUPS;
    const int t0 = blockIdx.x * NGROUPS + g;
    const int T = (t0 < n_tiles) ? ((n_tiles - 1 - t0) / GS + 1) : 0;

    // staging geometry: 128 threads, chunk c = rows c*8..c*8+7
    const int lrow_off = t128 >> 4;
    const int lcol     = (t128 & 15) * 8;
    const uint32_t sts_off = (uint32_t)(lrow_off * XH_ROWB) + (uint32_t)(lcol * 2);

    // epilogue over a j8 range (softplus + dot W2)
    #define EPI_RANGE(p, acc, LO, HI)                                          \
        _Pragma("unroll")                                                      \
        for (int j8 = (LO); j8 < (HI); j8++) {                                 \
            float2 bb = ldsf2(bbs + (uint32_t)(j8 * 32));                      \
            float2 ww = ldsf2(wbs + (uint32_t)(j8 * 32));                      \
            _Pragma("unroll")                                                  \
            for (int mt = 0; mt < 2; mt++) {                                   \
                sp_acc(p[mt][0], acc[mt][j8][0], bb.x, ww.x);                  \
                sp_acc(p[mt][0], acc[mt][j8][1], bb.y, ww.y);                  \
                sp_acc(p[mt][1], acc[mt][j8][2], bb.x, ww.x);                  \
                sp_acc(p[mt][1], acc[mt][j8][3], bb.y, ww.y);                  \
            }                                                                  \
        }

    if (T > 0) {
        // prologue stage of tile 0 into buffer 0
        {
            const float* src = x + (size_t)t0 * TILE_M * 128 + lcol;
            uint32_t dst = xgrp + sts_off;
            #pragma unroll
            for (int c = 0; c < 4; c++) {
                int row = c * 8 + lrow_off;
                float4 v0 = make_float4(0.f, 0.f, 0.f, 0.f), v1 = v0;
                if ((size_t)t0 * TILE_M + row < (size_t)n_nodes) {
                    v0 = *(const float4*)(src + (size_t)row * 128);
                    v1 = *(const float4*)(src + (size_t)row * 128 + 4);
                }
                sts128(dst + (uint32_t)(c * 8 * XH_ROWB),
                       pack_f16(v0.x, v0.y), pack_f16(v0.z, v0.w),
                       pack_f16(v1.x, v1.y), pack_f16(v1.z, v1.w));
            }
        }
        group_bar(g);

        for (int i = 0; i < T; i++) {
            const uint32_t xb = xgrp + (uint32_t)(i & 1) * XHB;

            // ---- MMA loop: acc[mt][j8][4] ----------------------------------
            float acc[2][4][4];
            #pragma unroll
            for (int mt = 0; mt < 2; mt++)
                #pragma unroll
                for (int j8 = 0; j8 < 4; j8++)
                    #pragma unroll
                    for (int e = 0; e < 4; e++) acc[mt][j8][e] = 0.0f;

            #pragma unroll
            for (int ks = 0; ks < 8; ks++) {
                uint32_t A0[4], A1[4];
                ldmatrix_x4(A0[0], A0[1], A0[2], A0[3],
                            xb + abase[0] + (uint32_t)(ks * 32));
                ldmatrix_x4(A1[0], A1[1], A1[2], A1[3],
                            xb + abase[1] + (uint32_t)(ks * 32));
                #pragma unroll
                for (int ntp = 0; ntp < 2; ntp++) {
                    uint32_t h0, h1, h2, h3;
                    ldmatrix_x4(h0, h1, h2, h3, bbase[ntp] + (uint32_t)(ks * 32));
                    mma_f32acc(acc[0][ntp * 2],     A0, h0, h2);
                    mma_f32acc(acc[0][ntp * 2 + 1], A0, h1, h3);
                    mma_f32acc(acc[1][ntp * 2],     A1, h0, h2);
                    mma_f32acc(acc[1][ntp * 2 + 1], A1, h1, h3);
                }
            }

            // ---- next-tile prefetch setup ----------------------------------
            const bool hn = (i + 1 < T);
            const long tnext = (long)t0 + (long)(i + 1) * GS;
            const float* srcn = x + (size_t)(hn ? tnext : 0) * TILE_M * 128 + lcol;
            const uint32_t xn = xgrp + (uint32_t)((i + 1) & 1) * XHB + sts_off;

            // prefetch scatter index (independent LDG, hidden under epilogue)
            int gidx = -1;
            if (t128 < 32) {
                long gn = ((long)t0 + (long)i * GS) * TILE_M + t128;
                if (gn < n_nodes) gidx = batch[gn];
            }

            float4 v0[2], v1[2];
            // LDG wave 1: chunks 0,1 (latency hidden under epi half 1)
            if (hn) {
                #pragma unroll
                for (int c = 0; c < 2; c++) {
                    int row = c * 8 + lrow_off;
                    v0[c] = make_float4(0.f, 0.f, 0.f, 0.f); v1[c] = v0[c];
                    if (tnext * TILE_M + row < (long)n_nodes) {
                        v0[c] = *(const float4*)(srcn + (size_t)row * 128);
                        v1[c] = *(const float4*)(srcn + (size_t)row * 128 + 4);
                    }
                }
            }

            float p[2][2];
            p[0][0] = p[0][1] = p[1][0] = p[1][1] = -c0;
            EPI_RANGE(p, acc, 0, 2)       // MUFU half 1 hides LDG wave 1

            if (hn) {
                #pragma unroll
                for (int c = 0; c < 2; c++)
                    sts128(xn + (uint32_t)(c * 8 * XH_ROWB),
                           pack_f16(v0[c].x, v0[c].y), pack_f16(v0[c].z, v0[c].w),
                           pack_f16(v1[c].x, v1[c].y), pack_f16(v1[c].z, v1[c].w));
                // LDG wave 2: chunks 2,3
                #pragma unroll
                for (int c = 0; c < 2; c++) {
                    int row = (c + 2) * 8 + lrow_off;
                    v0[c] = make_float4(0.f, 0.f, 0.f, 0.f); v1[c] = v0[c];
                    if (tnext * TILE_M + row < (long)n_nodes) {
                        v0[c] = *(const float4*)(srcn + (size_t)row * 128);
                        v1[c] = *(const float4*)(srcn + (size_t)row * 128 + 4);
                    }
                }
            }

            EPI_RANGE(p, acc, 2, 4)       // MUFU half 2 hides LDG wave 2

            // quad reduce + stage partials (also hides wave-2 latency)
            #pragma unroll
            for (int mt = 0; mt < 2; mt++)
                #pragma unroll
                for (int rr = 0; rr < 2; rr++) {
                    p[mt][rr] += __shfl_xor_sync(0xffffffffu, p[mt][rr], 1);
                    p[mt][rr] += __shfl_xor_sync(0xffffffffu, p[mt][rr], 2);
                }
            if (qc == 0) {
                #pragma unroll
                for (int mt = 0; mt < 2; mt++) {
                    s_partial[g][i & 1][wg][mt * 16 + qr]     = p[mt][0];
                    s_partial[g][i & 1][wg][mt * 16 + qr + 8] = p[mt][1];
                }
            }

            if (hn) {
                #pragma unroll
                for (int c = 0; c < 2; c++)
                    sts128(xn + (uint32_t)((c + 2) * 8 * XH_ROWB),
                           pack_f16(v0[c].x, v0[c].y), pack_f16(v0[c].z, v0[c].w),
                           pack_f16(v1[c].x, v1[c].y), pack_f16(v1[c].z, v1[c].w));
            }

            group_bar(g);   // single barrier: partials + next-buffer STS

            // scatter overlaps the next iteration (s_partial double-buffered)
            if (gidx >= 0) {
                float v = s_partial[g][i & 1][0][t128] + s_partial[g][i & 1][1][t128]
                        + s_partial[g][i & 1][2][t128] + s_partial[g][i & 1][3][t128];
                atomicAdd(&out[gidx], v);
            }
        }
    }
    #undef EPI_RANGE
}

// ---------------- launch -----------------------------------------------------

extern "C" void kernel_launch(void* const* d_in, const int* in_sizes, int n_in,
                              void* d_out, int out_size)
{
    const float* x     = (const float*)d_in[0];
    const float* W1    = (const float*)d_in[1];
    const float* b1    = (const float*)d_in[2];
    const float* W2    = (const float*)d_in[3];
    const int*   batch = (const int*)d_in[4];
    float* out = (float*)d_out;

    const int n_nodes = in_sizes[0] / 128;
    const int n_tiles = (n_nodes + TILE_M - 1) / TILE_M;

    prep_w1<<<64, 256>>>(W1, out, out_size);

    cudaFuncSetAttribute(fused_mlp_hmma,
                         cudaFuncAttributeMaxDynamicSharedMemorySize, SMEM_DYN);

    int sms = 148;
    cudaDeviceGetAttribute(&sms, cudaDevAttrMultiProcessorCount, 0);
    int work = (n_tiles + NGROUPS - 1) / NGROUPS;
    int grid = (work < 2 * sms) ? work : 2 * sms;

    fused_mlp_hmma<<<grid, NTHREADS, SMEM_DYN>>>(x, b1, W2, batch, out,
                                                 n_nodes, n_tiles);
}